// round 9
// baseline (speedup 1.0000x reference)
#include <cuda_runtime.h>
#include <cstdint>
#include <cstddef>

// Problem constants
#define BB 2
#define PP 4000
#define NPTS 4096
#define DD 64
#define DSC 64
#define MM 512
#define KK 8
#define NXX 432
#define NYY 496
#define HW (NXX*NYY)        // 214272

#define NSPLIT_PTS 16
#define PTS_PER_SPLIT (NPTS/NSPLIT_PTS)   // 256
#define NSPLIT_MEM 8
#define MEM_PER_SPLIT (MM/NSPLIT_MEM)     // 64
#define TILE_J 64
#define PTS_SLOTS (NSPLIT_PTS*KK)         // 128
#define MEM_SLOTS (NSPLIT_MEM*KK)         // 64
#define SLOT_STRIDE (PTS_SLOTS+MEM_SLOTS) // 192 per pillar: [0,128) pts, [128,192) mem
#define BPP (BB*PP)                       // 8000
#define PLANES 320
#define PLANES_PER_BLK 32

// ---- device scratch (no allocations allowed; 16B-aligned) ----
__device__ __align__(16) int   g_winner[BB*HW];
__device__ __align__(16) float g_topv[(size_t)BPP*SLOT_STRIDE];   // [g][slot]
__device__ __align__(16) int   g_topi[(size_t)BPP*SLOT_STRIDE];

// ---- packed fp32x2 helpers (Blackwell paired-FP32 pipe) ----
typedef unsigned long long u64t;
__device__ __forceinline__ u64t pk2(float x, float y) {
    u64t r; asm("mov.b64 %0, {%1, %2};" : "=l"(r) : "f"(x), "f"(y)); return r;
}
__device__ __forceinline__ void up2(u64t a, float& x, float& y) {
    asm("mov.b64 {%0, %1}, %2;" : "=f"(x), "=f"(y) : "l"(a));
}
__device__ __forceinline__ void fma2(u64t& d, u64t a, u64t b) {
    asm("fma.rn.f32x2 %0, %1, %2, %0;" : "+l"(d) : "l"(a), "l"(b));
}
// packed reduce: (e + o) as f32x2, then horizontal add
__device__ __forceinline__ float red2(u64t e, u64t o) {
    u64t s; asm("add.rn.f32x2 %0, %1, %2;" : "=l"(s) : "l"(e), "l"(o));
    float x, y; up2(s, x, y); return x + y;
}

// ---- register-resident top-8 insertion ----
__device__ __forceinline__ void ins8(float v, int id, float tv[KK], int ti[KK],
                                     float& vmin, int& pmin) {
    if (v > vmin) {
#pragma unroll
        for (int k = 0; k < KK; k++) if (k == pmin) { tv[k] = v; ti[k] = id; }
        vmin = tv[0]; pmin = 0;
#pragma unroll
        for (int k = 1; k < KK; k++) if (tv[k] < vmin) { vmin = tv[k]; pmin = k; }
    }
}

// ============================================================================
// Combined top-k kernel, 2 pillars per thread (A-tile register blocking).
//   blockIdx.y <  NSPLIT_PTS          : points split (256 rows)
//   blockIdx.y >= NSPLIT_PTS (8 more) : memory-weight split (64 rows)
// Each 128-thread block covers 256 pillars: p0 = bx*256+tid, p1 = p0+128.
// Every smem B element feeds 4 fma2 (2 pillars x even/odd) -> 71% fma density.
// ============================================================================
__global__ void __launch_bounds__(128, 1)
k_topk_all(const float* __restrict__ pillars,
           const float* __restrict__ points,
           const float* __restrict__ W)
{
    const int b   = blockIdx.z;
    const int y   = blockIdx.y;
    const int tid = threadIdx.x;
    const int p0  = blockIdx.x * 256 + tid;
    const int p1  = p0 + 128;

    const float* rsrc;
    int base, perSplit, slotBase;
    if (y < NSPLIT_PTS) {
        rsrc = points + (size_t)b * NPTS * DD;
        base = y * PTS_PER_SPLIT; perSplit = PTS_PER_SPLIT; slotBase = y * KK;
    } else {
        rsrc = W;
        base = (y - NSPLIT_PTS) * MEM_PER_SPLIT; perSplit = MEM_PER_SPLIT;
        slotBase = PTS_SLOTS + (y - NSPLIT_PTS) * KK;
    }

    __shared__ __align__(16) float spt[TILE_J * DD];

    // Both pillar vectors in registers (clamped row for inactive threads).
    u64t pr0[32], pr1[32];
    {
        const int q0 = (p0 < PP) ? p0 : (PP - 1);
        const int q1 = (p1 < PP) ? p1 : (PP - 1);
        const float4* a0 = (const float4*)(pillars + ((size_t)b * PP + q0) * DD);
        const float4* a1 = (const float4*)(pillars + ((size_t)b * PP + q1) * DD);
#pragma unroll
        for (int q = 0; q < 16; q++) {
            float4 v = a0[q];
            pr0[2*q] = pk2(v.x, v.y); pr0[2*q+1] = pk2(v.z, v.w);
        }
#pragma unroll
        for (int q = 0; q < 16; q++) {
            float4 v = a1[q];
            pr1[2*q] = pk2(v.x, v.y); pr1[2*q+1] = pk2(v.z, v.w);
        }
    }

    float tv0[KK], tv1[KK]; int ti0[KK], ti1[KK];
#pragma unroll
    for (int k = 0; k < KK; k++) {
        tv0[k] = -3.0e38f; ti0[k] = 0; tv1[k] = -3.0e38f; ti1[k] = 0;
    }
    float vmin0 = -3.0e38f, vmin1 = -3.0e38f; int pmin0 = 0, pmin1 = 0;

    const int ntiles = perSplit / TILE_J;
    for (int t = 0; t < ntiles; t++) {
        const int tb = base + t * TILE_J;
        const float4* gsrc = (const float4*)(rsrc + (size_t)tb * DD);
#pragma unroll
        for (int r = 0; r < 8; r++)
            ((float4*)spt)[r * 128 + tid] = gsrc[r * 128 + tid];
        __syncthreads();

        for (int j = 0; j < TILE_J; j += 4) {
            // accumulators: [pillar][row][even/odd] = 16 independent chains
            u64t A[2][4][2];
#pragma unroll
            for (int a = 0; a < 2; a++)
#pragma unroll
                for (int r = 0; r < 4; r++) { A[a][r][0] = 0; A[a][r][1] = 0; }

            const ulonglong2* r0 = (const ulonglong2*)&spt[(j+0)*DD];
            const ulonglong2* r1 = (const ulonglong2*)&spt[(j+1)*DD];
            const ulonglong2* r2 = (const ulonglong2*)&spt[(j+2)*DD];
            const ulonglong2* r3 = (const ulonglong2*)&spt[(j+3)*DD];
#pragma unroll
            for (int q = 0; q < 16; q++) {
                const u64t pe0 = pr0[2*q], po0 = pr0[2*q+1];
                const u64t pe1 = pr1[2*q], po1 = pr1[2*q+1];
                ulonglong2 x0 = r0[q], x1 = r1[q], x2 = r2[q], x3 = r3[q];
                fma2(A[0][0][0], pe0, x0.x); fma2(A[0][0][1], po0, x0.y);
                fma2(A[1][0][0], pe1, x0.x); fma2(A[1][0][1], po1, x0.y);
                fma2(A[0][1][0], pe0, x1.x); fma2(A[0][1][1], po0, x1.y);
                fma2(A[1][1][0], pe1, x1.x); fma2(A[1][1][1], po1, x1.y);
                fma2(A[0][2][0], pe0, x2.x); fma2(A[0][2][1], po0, x2.y);
                fma2(A[1][2][0], pe1, x2.x); fma2(A[1][2][1], po1, x2.y);
                fma2(A[0][3][0], pe0, x3.x); fma2(A[0][3][1], po0, x3.y);
                fma2(A[1][3][0], pe1, x3.x); fma2(A[1][3][1], po1, x3.y);
            }
#pragma unroll
            for (int r = 0; r < 4; r++) {
                ins8(red2(A[0][r][0], A[0][r][1]), tb + j + r, tv0, ti0, vmin0, pmin0);
                ins8(red2(A[1][r][0], A[1][r][1]), tb + j + r, tv1, ti1, vmin1, pmin1);
            }
        }
        __syncthreads();
    }

    if (p0 < PP) {
        const size_t o = (size_t)(b * PP + p0) * SLOT_STRIDE + slotBase;
#pragma unroll
        for (int k = 0; k < KK; k++) { g_topv[o + k] = tv0[k]; g_topi[o + k] = ti0[k]; }
    }
    if (p1 < PP) {
        const size_t o = (size_t)(b * PP + p1) * SLOT_STRIDE + slotBase;
#pragma unroll
        for (int k = 0; k < KK; k++) { g_topv[o + k] = tv1[k]; g_topi[o + k] = ti1[k]; }
    }
}

// ============================================================================
// Warp-per-task merge: 16000 warps (8000 pillars x {point, mem}).
// ============================================================================
__global__ void __launch_bounds__(256)
k_merge_warp(const float* __restrict__ points, const float* __restrict__ W,
             float* __restrict__ out4, float* __restrict__ out5)
{
    const int wid  = blockIdx.x * 8 + (threadIdx.x >> 5);
    if (wid >= 2 * BPP) return;
    const int lane = threadIdx.x & 31;
    const int g    = wid >> 1;
    const bool isMem = (wid & 1);
    const int b = g / PP;

    const float* rsrc = isMem ? W : points + (size_t)b * NPTS * DD;
    const int base = isMem ? PTS_SLOTS : 0;
    const int nc   = isMem ? (MEM_SLOTS / 32) : (PTS_SLOTS / 32);   // 2 or 4
    float* dst = (isMem ? out5 : out4) + (size_t)g * DD;

    const size_t o = (size_t)g * SLOT_STRIDE + base;
    float cv[4]; int ci[4];
#pragma unroll
    for (int j = 0; j < 4; j++) {
        if (j < nc) { cv[j] = g_topv[o + j*32 + lane]; ci[j] = g_topi[o + j*32 + lane]; }
        else        { cv[j] = -3.0e38f; ci[j] = 0x7FFFFFFF; }
    }

    float tvk[KK]; int tik[KK];
#pragma unroll
    for (int k = 0; k < KK; k++) {
        float bv = cv[0]; int bi = ci[0];
#pragma unroll
        for (int j = 1; j < 4; j++)
            if (cv[j] > bv || (cv[j] == bv && ci[j] < bi)) { bv = cv[j]; bi = ci[j]; }
#pragma unroll
        for (int off = 16; off; off >>= 1) {
            float ov = __shfl_xor_sync(0xFFFFFFFFu, bv, off);
            int   oi = __shfl_xor_sync(0xFFFFFFFFu, bi, off);
            if (ov > bv || (ov == bv && oi < bi)) { bv = ov; bi = oi; }
        }
        tvk[k] = bv; tik[k] = bi;
#pragma unroll
        for (int j = 0; j < 4; j++)
            if (ci[j] == bi) cv[j] = -3.0e38f;
    }

    const float m = tvk[0];
    float w[KK]; float ssum = 0.0f;
#pragma unroll
    for (int k = 0; k < KK; k++) { w[k] = expf(tvk[k] - m); ssum += w[k]; }
    const float inv = 1.0f / ssum;

    float ax = 0.f, ay = 0.f;
#pragma unroll
    for (int k = 0; k < KK; k++) {
        const float wk = w[k] * inv;
        const float2 r = *(const float2*)&rsrc[(size_t)tik[k] * DD + 2*lane];
        ax += wk * r.x; ay += wk * r.y;
    }
    *(float2*)&dst[2*lane] = make_float2(ax, ay);
}

// ============================================================================
// Winner pass (last-wins scatter semantics: max pillar index per cell)
// ============================================================================
__global__ void k_winner_init() {
    int i = blockIdx.x * 256 + threadIdx.x;
    if (i < BB * HW) g_winner[i] = -1;
}

__global__ void k_winner_mark(const int* __restrict__ idx) {
    int g = blockIdx.x * 256 + threadIdx.x;
    if (g >= BPP) return;
    int b = g / PP;
    atomicMax(&g_winner[b * HW + idx[g]], g - b * PP);
}

// ============================================================================
// Dense gather-fill with streaming stores. Each thread owns 4 consecutive grid
// cells, loops over 32 channel-planes writing coalesced float4 __stcs stores.
// ============================================================================
__global__ void __launch_bounds__(256)
k_fill(const float* __restrict__ pillars, const float* __restrict__ scale,
       const float* __restrict__ pos_point, const float* __restrict__ pos_mem,
       float* __restrict__ out)
{
    const int b = blockIdx.z;
    const int hw = (blockIdx.x * 256 + threadIdx.x) * 4;
    if (hw >= HW) return;

    const int4 w = *(const int4*)&g_winner[b * HW + hw];
    const int wm = max(max(w.x, w.y), max(w.z, w.w));
    const bool any = (wm >= 0);
    const size_t G1 = (size_t)BB * 128 * HW;

    const int t0 = blockIdx.y * PLANES_PER_BLK;
#pragma unroll 4
    for (int t = t0; t < t0 + PLANES_PER_BLK; t++) {
        const float* A; int cc; size_t ob;
        if (t < 64)       { A = pillars;   cc = t;       ob = ((size_t)b*128 + t) * HW; }
        else if (t < 128) { A = pos_mem;   cc = t - 64;  ob = ((size_t)b*128 + t) * HW; }
        else if (t < 192) { A = pillars;   cc = t - 128; ob = G1 + ((size_t)b*128 + (t-128)) * HW; }
        else if (t < 256) { A = pos_point; cc = t - 192; ob = G1 + ((size_t)b*128 + (t-128)) * HW; }
        else              { A = scale;     cc = t - 256; ob = 2*G1 + ((size_t)b*64 + (t-256)) * HW; }

        float4 v = make_float4(0.f, 0.f, 0.f, 0.f);
        if (any) {
            const float* Ab = A + (size_t)b * PP * 64 + cc;
            if (w.x >= 0) v.x = Ab[(size_t)w.x * 64];
            if (w.y >= 0) v.y = Ab[(size_t)w.y * 64];
            if (w.z >= 0) v.z = Ab[(size_t)w.z * 64];
            if (w.w >= 0) v.w = Ab[(size_t)w.w * 64];
        }
        __stcs(reinterpret_cast<float4*>(out + ob + hw), v);
    }
}

// ============================================================================
// kernel_launch — graph-capturable, allocation-free.
// Inputs: pillar_features, pillar_scale_features, point_features,
//         memory_weight, indices
// Output: sp, sp_point, sp_scale, pos_point, pos_mem (fp32, concatenated)
// ============================================================================
extern "C" void kernel_launch(void* const* d_in, const int* in_sizes, int n_in,
                              void* d_out, int out_size)
{
    const float* pillars = (const float*)d_in[0];
    const float* scale   = (const float*)d_in[1];
    const float* points  = (const float*)d_in[2];
    const float* W       = (const float*)d_in[3];
    const int*   idx     = (const int*)  d_in[4];
    float* out = (float*)d_out;

    const size_t sz12  = (size_t)BB * 128 * HW;
    const size_t sz3   = (size_t)BB * 64 * HW;
    const size_t grids = 2 * sz12 + sz3;
    float* out4 = out + grids;                   // point_positive [B*P, 64]
    float* out5 = out4 + (size_t)BPP * DD;       // memory_positive [B*P, 64]

    // winner resolution first (only depends on idx)
    k_winner_init<<<(BB * HW + 255) / 256, 256>>>();
    k_winner_mark<<<(BPP + 255) / 256, 256>>>(idx);

    // both attention matmuls + top-8, 2 pillars/thread (768 blocks)
    k_topk_all<<<dim3((PP + 255) / 256, NSPLIT_PTS + NSPLIT_MEM, BB), 128>>>(
        pillars, points, W);

    // warp-per-task merge: 16000 warps
    k_merge_warp<<<(2 * BPP + 7) / 8, 256>>>(points, W, out4, out5);

    // dense gather-fill of all three grids (no memset needed)
    k_fill<<<dim3((HW / 4 + 255) / 256, PLANES / PLANES_PER_BLK, BB), 256>>>(
        pillars, scale, out4, out5, out);
}

// round 11
// speedup vs baseline: 1.2903x; 1.2903x over previous
#include <cuda_runtime.h>
#include <cstdint>
#include <cstddef>

// Problem constants
#define BB 2
#define PP 4000
#define NPTS 4096
#define DD 64
#define DSC 64
#define MM 512
#define KK 8
#define NXX 432
#define NYY 496
#define HW (NXX*NYY)        // 214272

#define NSPLIT_PTS 16
#define PTS_PER_SPLIT (NPTS/NSPLIT_PTS)   // 256
#define NSPLIT_MEM 8
#define MEM_PER_SPLIT (MM/NSPLIT_MEM)     // 64
#define TILE_J 64
#define PTS_SLOTS (NSPLIT_PTS*KK)         // 128
#define MEM_SLOTS (NSPLIT_MEM*KK)         // 64
#define SLOT_STRIDE (PTS_SLOTS+MEM_SLOTS) // 192 per pillar: [0,128) pts, [128,192) mem
#define BPP (BB*PP)                       // 8000

// ---- device scratch (no allocations allowed; 16B-aligned) ----
__device__ __align__(16) int   g_winner[BB*HW];
__device__ __align__(16) float g_topv[(size_t)BPP*SLOT_STRIDE];   // [g][slot]
__device__ __align__(16) int   g_topi[(size_t)BPP*SLOT_STRIDE];

// ---- packed fp32x2 helpers (Blackwell paired-FP32 pipe) ----
typedef unsigned long long u64t;
__device__ __forceinline__ u64t pk2(float x, float y) {
    u64t r; asm("mov.b64 %0, {%1, %2};" : "=l"(r) : "f"(x), "f"(y)); return r;
}
__device__ __forceinline__ void up2(u64t a, float& x, float& y) {
    asm("mov.b64 {%0, %1}, %2;" : "=f"(x), "=f"(y) : "l"(a));
}
__device__ __forceinline__ void fma2(u64t& d, u64t a, u64t b) {
    asm("fma.rn.f32x2 %0, %1, %2, %0;" : "+l"(d) : "l"(a), "l"(b));
}

// ---- register-resident top-8 insertion ----
__device__ __forceinline__ void ins8(float v, int id, float tv[KK], int ti[KK],
                                     float& vmin, int& pmin) {
    if (v > vmin) {
#pragma unroll
        for (int k = 0; k < KK; k++) if (k == pmin) { tv[k] = v; ti[k] = id; }
        vmin = tv[0]; pmin = 0;
#pragma unroll
        for (int k = 1; k < KK; k++) if (tv[k] < vmin) { vmin = tv[k]; pmin = k; }
    }
}

// ============================================================================
// Combined top-k kernel (proven R6 version): both matmuls in ONE launch.
// One thread = one pillar; pillar vector in 32 packed f32x2 registers.
// ============================================================================
__global__ void __launch_bounds__(128)
k_topk_all(const float* __restrict__ pillars,
           const float* __restrict__ points,
           const float* __restrict__ W)
{
    const int b = blockIdx.z;
    const int y = blockIdx.y;
    const int p = blockIdx.x * 128 + threadIdx.x;
    const bool active = (p < PP);

    const float* rsrc;
    int base, perSplit, slotBase;
    if (y < NSPLIT_PTS) {
        rsrc = points + (size_t)b * NPTS * DD;
        base = y * PTS_PER_SPLIT; perSplit = PTS_PER_SPLIT; slotBase = y * KK;
    } else {
        rsrc = W;
        base = (y - NSPLIT_PTS) * MEM_PER_SPLIT; perSplit = MEM_PER_SPLIT;
        slotBase = PTS_SLOTS + (y - NSPLIT_PTS) * KK;
    }

    __shared__ __align__(16) float spt[TILE_J * DD];

    u64t pr[32];
    if (active) {
        const float4* prow = (const float4*)(pillars + ((size_t)b * PP + p) * DD);
#pragma unroll
        for (int q = 0; q < 16; q++) {
            float4 v = prow[q];
            pr[2*q]   = pk2(v.x, v.y);
            pr[2*q+1] = pk2(v.z, v.w);
        }
    }

    float tv[KK]; int ti[KK];
#pragma unroll
    for (int k = 0; k < KK; k++) { tv[k] = -3.0e38f; ti[k] = 0; }
    float vmin = -3.0e38f; int pmin = 0;

    const int ntiles = perSplit / TILE_J;
    for (int t = 0; t < ntiles; t++) {
        const int tb = base + t * TILE_J;
        const float4* gsrc = (const float4*)(rsrc + (size_t)tb * DD);
#pragma unroll
        for (int r = 0; r < 8; r++)
            ((float4*)spt)[r * 128 + threadIdx.x] = gsrc[r * 128 + threadIdx.x];
        __syncthreads();

        if (active) {
            for (int j = 0; j < TILE_J; j += 4) {
                u64t a0e=0,a0o=0,a1e=0,a1o=0,a2e=0,a2o=0,a3e=0,a3o=0;
                const ulonglong2* r0 = (const ulonglong2*)&spt[(j+0)*DD];
                const ulonglong2* r1 = (const ulonglong2*)&spt[(j+1)*DD];
                const ulonglong2* r2 = (const ulonglong2*)&spt[(j+2)*DD];
                const ulonglong2* r3 = (const ulonglong2*)&spt[(j+3)*DD];
#pragma unroll
                for (int q = 0; q < 16; q++) {
                    ulonglong2 x0 = r0[q], x1 = r1[q], x2 = r2[q], x3 = r3[q];
                    fma2(a0e, pr[2*q], x0.x); fma2(a0o, pr[2*q+1], x0.y);
                    fma2(a1e, pr[2*q], x1.x); fma2(a1o, pr[2*q+1], x1.y);
                    fma2(a2e, pr[2*q], x2.x); fma2(a2o, pr[2*q+1], x2.y);
                    fma2(a3e, pr[2*q], x3.x); fma2(a3o, pr[2*q+1], x3.y);
                }
                float xa, xb, ya, yb, v;
                up2(a0e, xa, xb); up2(a0o, ya, yb); v = (xa + ya) + (xb + yb);
                ins8(v, tb + j + 0, tv, ti, vmin, pmin);
                up2(a1e, xa, xb); up2(a1o, ya, yb); v = (xa + ya) + (xb + yb);
                ins8(v, tb + j + 1, tv, ti, vmin, pmin);
                up2(a2e, xa, xb); up2(a2o, ya, yb); v = (xa + ya) + (xb + yb);
                ins8(v, tb + j + 2, tv, ti, vmin, pmin);
                up2(a3e, xa, xb); up2(a3o, ya, yb); v = (xa + ya) + (xb + yb);
                ins8(v, tb + j + 3, tv, ti, vmin, pmin);
            }
        }
        __syncthreads();
    }

    if (active) {
        const size_t o = (size_t)(b * PP + p) * SLOT_STRIDE + slotBase;
#pragma unroll
        for (int k = 0; k < KK; k++) { g_topv[o + k] = tv[k]; g_topi[o + k] = ti[k]; }
    }
}

// ============================================================================
// Warp-per-task merge (proven R6 version): 16000 warps.
// ============================================================================
__global__ void __launch_bounds__(256)
k_merge_warp(const float* __restrict__ points, const float* __restrict__ W,
             float* __restrict__ out4, float* __restrict__ out5)
{
    const int wid  = blockIdx.x * 8 + (threadIdx.x >> 5);
    if (wid >= 2 * BPP) return;
    const int lane = threadIdx.x & 31;
    const int g    = wid >> 1;
    const bool isMem = (wid & 1);
    const int b = g / PP;

    const float* rsrc = isMem ? W : points + (size_t)b * NPTS * DD;
    const int base = isMem ? PTS_SLOTS : 0;
    const int nc   = isMem ? (MEM_SLOTS / 32) : (PTS_SLOTS / 32);   // 2 or 4
    float* dst = (isMem ? out5 : out4) + (size_t)g * DD;

    const size_t o = (size_t)g * SLOT_STRIDE + base;
    float cv[4]; int ci[4];
#pragma unroll
    for (int j = 0; j < 4; j++) {
        if (j < nc) { cv[j] = g_topv[o + j*32 + lane]; ci[j] = g_topi[o + j*32 + lane]; }
        else        { cv[j] = -3.0e38f; ci[j] = 0x7FFFFFFF; }
    }

    float tvk[KK]; int tik[KK];
#pragma unroll
    for (int k = 0; k < KK; k++) {
        float bv = cv[0]; int bi = ci[0];
#pragma unroll
        for (int j = 1; j < 4; j++)
            if (cv[j] > bv || (cv[j] == bv && ci[j] < bi)) { bv = cv[j]; bi = ci[j]; }
#pragma unroll
        for (int off = 16; off; off >>= 1) {
            float ov = __shfl_xor_sync(0xFFFFFFFFu, bv, off);
            int   oi = __shfl_xor_sync(0xFFFFFFFFu, bi, off);
            if (ov > bv || (ov == bv && oi < bi)) { bv = ov; bi = oi; }
        }
        tvk[k] = bv; tik[k] = bi;
#pragma unroll
        for (int j = 0; j < 4; j++)
            if (ci[j] == bi) cv[j] = -3.0e38f;
    }

    const float m = tvk[0];
    float w[KK]; float ssum = 0.0f;
#pragma unroll
    for (int k = 0; k < KK; k++) { w[k] = expf(tvk[k] - m); ssum += w[k]; }
    const float inv = 1.0f / ssum;

    float ax = 0.f, ay = 0.f;
#pragma unroll
    for (int k = 0; k < KK; k++) {
        const float wk = w[k] * inv;
        const float2 r = *(const float2*)&rsrc[(size_t)tik[k] * DD + 2*lane];
        ax += wk * r.x; ay += wk * r.y;
    }
    *(float2*)&dst[2*lane] = make_float2(ax, ay);
}

// ============================================================================
// Winner pass (last-wins scatter semantics: max pillar index per cell)
// ============================================================================
__global__ void k_winner_init() {
    int i = blockIdx.x * 256 + threadIdx.x;
    if (i < BB * HW) g_winner[i] = -1;
}

__global__ void k_winner_mark(const int* __restrict__ idx) {
    int g = blockIdx.x * 256 + threadIdx.x;
    if (g >= BPP) return;
    int b = g / PP;
    atomicMax(&g_winner[b * HW + idx[g]], g - b * PP);
}

// ============================================================================
// Fill, split into input-only (static) and merge-dependent (dyn) plane sets so
// the static 329 MB streams concurrently with the compute-bound topk kernel.
// ============================================================================

// 192 planes: t<64 grid1/pillars, t<128 grid2/pillars, else grid3/scale
__global__ void __launch_bounds__(256)
k_fill_static(const float* __restrict__ pillars, const float* __restrict__ scale,
              float* __restrict__ out)
{
    const int b = blockIdx.z;
    const int hw = (blockIdx.x * 256 + threadIdx.x) * 4;
    if (hw >= HW) return;

    const int4 w = *(const int4*)&g_winner[b * HW + hw];
    const bool any = (max(max(w.x, w.y), max(w.z, w.w)) >= 0);
    const size_t G1 = (size_t)BB * 128 * HW;

    const int t0 = blockIdx.y * 32;
#pragma unroll 4
    for (int t = t0; t < t0 + 32; t++) {
        const float* A; int cc; size_t ob;
        if (t < 64)       { A = pillars; cc = t;       ob = ((size_t)b*128 + t) * HW; }
        else if (t < 128) { A = pillars; cc = t - 64;  ob = G1 + ((size_t)b*128 + (t-64)) * HW; }
        else              { A = scale;   cc = t - 128; ob = 2*G1 + ((size_t)b*64 + (t-128)) * HW; }

        float4 v = make_float4(0.f, 0.f, 0.f, 0.f);
        if (any) {
            const float* Ab = A + (size_t)b * PP * 64 + cc;
            if (w.x >= 0) v.x = Ab[(size_t)w.x * 64];
            if (w.y >= 0) v.y = Ab[(size_t)w.y * 64];
            if (w.z >= 0) v.z = Ab[(size_t)w.z * 64];
            if (w.w >= 0) v.w = Ab[(size_t)w.w * 64];
        }
        *(float4*)(out + ob + hw) = v;
    }
}

// 128 planes: t<64 grid1/pos_mem (ch 64+t), else grid2/pos_point (ch 64+(t-64))
__global__ void __launch_bounds__(256)
k_fill_dyn(const float* __restrict__ pos_point, const float* __restrict__ pos_mem,
           float* __restrict__ out)
{
    const int b = blockIdx.z;
    const int hw = (blockIdx.x * 256 + threadIdx.x) * 4;
    if (hw >= HW) return;

    const int4 w = *(const int4*)&g_winner[b * HW + hw];
    const bool any = (max(max(w.x, w.y), max(w.z, w.w)) >= 0);
    const size_t G1 = (size_t)BB * 128 * HW;

    const int t0 = blockIdx.y * 32;
#pragma unroll 4
    for (int t = t0; t < t0 + 32; t++) {
        const float* A; int cc; size_t ob;
        if (t < 64) { A = pos_mem;   cc = t;      ob = ((size_t)b*128 + 64 + t) * HW; }
        else        { A = pos_point; cc = t - 64; ob = G1 + ((size_t)b*128 + 64 + (t-64)) * HW; }

        float4 v = make_float4(0.f, 0.f, 0.f, 0.f);
        if (any) {
            const float* Ab = A + (size_t)b * PP * 64 + cc;
            if (w.x >= 0) v.x = Ab[(size_t)w.x * 64];
            if (w.y >= 0) v.y = Ab[(size_t)w.y * 64];
            if (w.z >= 0) v.z = Ab[(size_t)w.z * 64];
            if (w.w >= 0) v.w = Ab[(size_t)w.w * 64];
        }
        *(float4*)(out + ob + hw) = v;
    }
}

// ============================================================================
// kernel_launch — graph-capturable, allocation-free, two-stream fork/join.
// DAG:  s0: [fork e0] topk ── merge ── [e2] ─────────────── [wait e3]
//       s1: [wait e0] winner_init ── winner_mark ── fill_static ── [wait e2]
//           ── fill_dyn ── [e3]
// ============================================================================
extern "C" void kernel_launch(void* const* d_in, const int* in_sizes, int n_in,
                              void* d_out, int out_size)
{
    const float* pillars = (const float*)d_in[0];
    const float* scale   = (const float*)d_in[1];
    const float* points  = (const float*)d_in[2];
    const float* W       = (const float*)d_in[3];
    const int*   idx     = (const int*)  d_in[4];
    float* out = (float*)d_out;

    const size_t sz12  = (size_t)BB * 128 * HW;
    const size_t sz3   = (size_t)BB * 64 * HW;
    const size_t grids = 2 * sz12 + sz3;
    float* out4 = out + grids;                   // point_positive [B*P, 64]
    float* out5 = out4 + (size_t)BPP * DD;       // memory_positive [B*P, 64]

    // one-time host-side resources (no device memory; identical work per call)
    static cudaStream_t s1 = nullptr;
    static cudaEvent_t e0, e2, e3;
    if (!s1) {
        cudaStreamCreateWithFlags(&s1, cudaStreamNonBlocking);
        cudaEventCreateWithFlags(&e0, cudaEventDisableTiming);
        cudaEventCreateWithFlags(&e2, cudaEventDisableTiming);
        cudaEventCreateWithFlags(&e3, cudaEventDisableTiming);
    }

    // fork s1 from the origin stream
    cudaEventRecord(e0, 0);
    cudaStreamWaitEvent(s1, e0, 0);

    // s1: winner resolution + input-only dense fill (329 MB, DRAM-bound)
    k_winner_init<<<(BB * HW + 255) / 256, 256, 0, s1>>>();
    k_winner_mark<<<(BPP + 255) / 256, 256, 0, s1>>>(idx);
    k_fill_static<<<dim3((HW / 4 + 255) / 256, 6, BB), 256, 0, s1>>>(
        pillars, scale, out);

    // s0: both attention matmuls + top-8 (compute-bound, DRAM idle) + merge
    k_topk_all<<<dim3((PP + 127) / 128, NSPLIT_PTS + NSPLIT_MEM, BB), 128>>>(
        pillars, points, W);
    k_merge_warp<<<(2 * BPP + 7) / 8, 256>>>(points, W, out4, out5);
    cudaEventRecord(e2, 0);

    // s1: merge-dependent fill (219 MB) after merge completes
    cudaStreamWaitEvent(s1, e2, 0);
    k_fill_dyn<<<dim3((HW / 4 + 255) / 256, 4, BB), 256, 0, s1>>>(
        out4, out5, out);
    cudaEventRecord(e3, s1);

    // join back to origin stream
    cudaStreamWaitEvent(0, e3, 0);
}